// round 4
// baseline (speedup 1.0000x reference)
#include <cuda_runtime.h>
#include <cuda_fp16.h>

#define NN 100000
#define EE 3200000
#define GG 2048
#define HH 64
#define SCAN_BS 512

// Scratch (device globals — no allocation allowed).
// fp16 tensors declared as uint4 arrays to guarantee 16B alignment.
__device__ uint4   d_uh[NN * 8];     // (h @ W) * dinv, fp16, 8 uint4 (=64 halves) per node
__device__ uint4   d_hh[NN * 8];     // node features h, fp16
__device__ float   d_dinv[NN];       // rsqrt(deg+1)
__device__ int     d_degi[NN];       // in-degree (targets)
__device__ int     d_off[NN];        // CSR offsets
__device__ int     d_epos[EE];       // per-edge rank within its target
__device__ int     d_csr[EE];        // source node per incoming edge, grouped by target
__device__ int     d_bsum[1024];     // scan block sums

// ---------------------------------------------------------------- init
__global__ void k_init(int n) {
    int i = blockIdx.x * blockDim.x + threadIdx.x;
    if (i < n) d_degi[i] = 0;
}

// in-degree over targets + per-edge rank
__global__ void k_deg(const int* __restrict__ col, int e_cnt) {
    int e = blockIdx.x * blockDim.x + threadIdx.x;
    if (e >= e_cnt) return;
    d_epos[e] = atomicAdd(&d_degi[col[e]], 1);
}

// ---------------------------------------------------------------- scans (warp-shuffle)
__device__ __forceinline__ int warp_iscan(int v) {
    int lane = threadIdx.x & 31;
#pragma unroll
    for (int o = 1; o < 32; o <<= 1) {
        int t = __shfl_up_sync(0xFFFFFFFFu, v, o);
        if (lane >= o) v += t;
    }
    return v;
}

__global__ void k_scan1(int n) {  // block = SCAN_BS = 512
    __shared__ int ws[16];
    int t = threadIdx.x, i = blockIdx.x * SCAN_BS + t;
    int lane = t & 31, wid = t >> 5;
    int v = (i < n) ? d_degi[i] : 0;
    int s = warp_iscan(v);                 // inclusive within warp
    if (lane == 31) ws[wid] = s;
    __syncthreads();
    if (wid == 0) {
        int wv = (lane < 16) ? ws[lane] : 0;
        int wsum = warp_iscan(wv);
        if (lane < 16) ws[lane] = wsum;
    }
    __syncthreads();
    int base = (wid > 0) ? ws[wid - 1] : 0;
    if (i < n) d_off[i] = base + s - v;    // exclusive
    if (t == SCAN_BS - 1) d_bsum[blockIdx.x] = base + s;
}

__global__ void k_scan2(int nb) {  // single block, 1024 threads
    __shared__ int ws[32];
    int t = threadIdx.x, lane = t & 31, wid = t >> 5;
    int v = (t < nb) ? d_bsum[t] : 0;
    int s = warp_iscan(v);
    if (lane == 31) ws[wid] = s;
    __syncthreads();
    if (wid == 0) {
        int wv = ws[lane];
        int wsum = warp_iscan(wv);
        ws[lane] = wsum;
    }
    __syncthreads();
    int base = (wid > 0) ? ws[wid - 1] : 0;
    if (t < nb) d_bsum[t] = base + s - v;  // exclusive
}

__global__ void k_scan3(int n) {
    int i = blockIdx.x * blockDim.x + threadIdx.x;
    if (i >= n) return;
    int off = d_off[i] + d_bsum[i / SCAN_BS];
    d_off[i] = off;
    d_dinv[i] = rsqrtf((float)d_degi[i] + 1.0f);  // +1 self-loop
}

// CSR fill: plain store via precomputed rank (no atomics)
__global__ void k_fill(const int* __restrict__ rowi, const int* __restrict__ coli, int e_cnt) {
    int e = blockIdx.x * blockDim.x + threadIdx.x;
    if (e >= e_cnt) return;
    d_csr[__ldg(&d_off[coli[e]]) + d_epos[e]] = rowi[e];
}

// ---------------------------------------------------------------- GEMM: u = (h @ W) * dinv  -> fp16
// layer 0 reads h rows from emb[x[row]] (fused embedding); later layers read fp16 h
__global__ void __launch_bounds__(256) k_gemm(const float* __restrict__ W,
                                              const int* __restrict__ x,
                                              const float* __restrict__ emb,
                                              int layer, int n) {
    __shared__ float4 sW[64 * 16];
    __shared__ float sh[64 * 68];

    int tid = threadIdx.x;
    int row0 = blockIdx.x * 64;

    const float4* W4 = (const float4*)W;
#pragma unroll
    for (int i = 0; i < 4; i++) sW[tid + 256 * i] = W4[tid + 256 * i];

    if (layer == 0) {
        const float4* emb4 = (const float4*)emb;
#pragma unroll
        for (int i = 0; i < 4; i++) {
            int l = tid + 256 * i;
            int r = l >> 4, c4 = l & 15;
            int grow = row0 + r;
            float4 v = make_float4(0.f, 0.f, 0.f, 0.f);
            if (grow < n) {
                int vx = __ldg(&x[grow]);
                v = __ldg(&emb4[vx * 16 + c4]);
            }
            ((float4*)sh)[r * 17 + c4] = v;
        }
    } else {
#pragma unroll
        for (int i = 0; i < 2; i++) {
            int l = tid + 256 * i;
            int r = l >> 3, c8 = l & 7;       // 8 uint4 per row
            int grow = row0 + r;
            uint4 uv = make_uint4(0, 0, 0, 0);
            if (grow < n) uv = d_hh[grow * 8 + c8];
            float2 f0 = __half22float2(*(__half2*)&uv.x);
            float2 f1 = __half22float2(*(__half2*)&uv.y);
            float2 f2 = __half22float2(*(__half2*)&uv.z);
            float2 f3 = __half22float2(*(__half2*)&uv.w);
            float* dst = &sh[r * 68 + c8 * 8];
            ((float4*)dst)[0] = make_float4(f0.x, f0.y, f1.x, f1.y);
            ((float4*)dst)[1] = make_float4(f2.x, f2.y, f3.x, f3.y);
        }
    }
    __syncthreads();

    int r = tid >> 2, q = tid & 3;
    float4 a0 = make_float4(0.f, 0.f, 0.f, 0.f), a1 = a0, a2 = a0, a3 = a0;

#pragma unroll 16
    for (int k = 0; k < 64; k++) {
        float hv = sh[r * 68 + k];
        float4 w0 = sW[k * 16 + q * 4 + 0];
        float4 w1 = sW[k * 16 + q * 4 + 1];
        float4 w2 = sW[k * 16 + q * 4 + 2];
        float4 w3 = sW[k * 16 + q * 4 + 3];
        a0.x = fmaf(hv, w0.x, a0.x); a0.y = fmaf(hv, w0.y, a0.y);
        a0.z = fmaf(hv, w0.z, a0.z); a0.w = fmaf(hv, w0.w, a0.w);
        a1.x = fmaf(hv, w1.x, a1.x); a1.y = fmaf(hv, w1.y, a1.y);
        a1.z = fmaf(hv, w1.z, a1.z); a1.w = fmaf(hv, w1.w, a1.w);
        a2.x = fmaf(hv, w2.x, a2.x); a2.y = fmaf(hv, w2.y, a2.y);
        a2.z = fmaf(hv, w2.z, a2.z); a2.w = fmaf(hv, w2.w, a2.w);
        a3.x = fmaf(hv, w3.x, a3.x); a3.y = fmaf(hv, w3.y, a3.y);
        a3.z = fmaf(hv, w3.z, a3.z); a3.w = fmaf(hv, w3.w, a3.w);
    }

    int row = row0 + r;
    if (row < n) {
        float dv = __ldg(&d_dinv[row]);
        uint4 o0, o1;
        __half2 t0, t1;
        t0 = __float22half2_rn(make_float2(a0.x * dv, a0.y * dv));
        t1 = __float22half2_rn(make_float2(a0.z * dv, a0.w * dv));
        o0.x = *(unsigned*)&t0; o0.y = *(unsigned*)&t1;
        t0 = __float22half2_rn(make_float2(a1.x * dv, a1.y * dv));
        t1 = __float22half2_rn(make_float2(a1.z * dv, a1.w * dv));
        o0.z = *(unsigned*)&t0; o0.w = *(unsigned*)&t1;
        t0 = __float22half2_rn(make_float2(a2.x * dv, a2.y * dv));
        t1 = __float22half2_rn(make_float2(a2.z * dv, a2.w * dv));
        o1.x = *(unsigned*)&t0; o1.y = *(unsigned*)&t1;
        t0 = __float22half2_rn(make_float2(a3.x * dv, a3.y * dv));
        t1 = __float22half2_rn(make_float2(a3.z * dv, a3.w * dv));
        o1.z = *(unsigned*)&t0; o1.w = *(unsigned*)&t1;
        d_uh[row * 8 + q * 2 + 0] = o0;
        d_uh[row * 8 + q * 2 + 1] = o1;
    }
}

// ---------------------------------------------------------------- gather + epilogue
// 8 threads/node, each owns 8 channels. CSR indices loaded coalesced (1 per lane
// per 8-edge chunk) and broadcast via shfl width=8. fp32 accumulate, fp16 h out.
__global__ void __launch_bounds__(256) k_gather(const float* __restrict__ b, int layer, int n) {
    int idx = blockIdx.x * blockDim.x + threadIdx.x;
    int nd = idx >> 3;
    if (nd >= n) return;
    int p = idx & 7;
    int lane = threadIdx.x & 31;
    unsigned grpmask = 0xFFu << (lane & ~7);

    int beg = __ldg(&d_off[nd]);
    int deg = __ldg(&d_degi[nd]);

    float a0 = 0.f, a1 = 0.f, a2 = 0.f, a3 = 0.f,
          a4 = 0.f, a5 = 0.f, a6 = 0.f, a7 = 0.f;

#define ACC8(v) do {                                                  \
        float2 f;                                                     \
        f = __half22float2(*(__half2*)&(v).x); a0 += f.x; a1 += f.y;  \
        f = __half22float2(*(__half2*)&(v).y); a2 += f.x; a3 += f.y;  \
        f = __half22float2(*(__half2*)&(v).z); a4 += f.x; a5 += f.y;  \
        f = __half22float2(*(__half2*)&(v).w); a6 += f.x; a7 += f.y;  \
    } while (0)

    uint4 vs = d_uh[nd * 8 + p];  // self-loop term
    ACC8(vs);

    for (int k = 0; k < deg; k += 8) {
        int si = 0;
        if (k + p < deg) si = __ldg(&d_csr[beg + k + p]);
        int lim = deg - k;
#pragma unroll
        for (int j = 0; j < 8; j++) {
            if (j < lim) {
                int s = __shfl_sync(grpmask, si, j, 8);
                uint4 v = __ldg(&d_uh[s * 8 + p]);
                ACC8(v);
            }
        }
    }
#undef ACC8

    float dv = __ldg(&d_dinv[nd]);
    const float4* b4 = (const float4*)b;
    float4 bb0 = __ldg(&b4[p * 2 + 0]);
    float4 bb1 = __ldg(&b4[p * 2 + 1]);

    float v0 = fmaxf(fmaf(dv, a0, bb0.x), 0.f);
    float v1 = fmaxf(fmaf(dv, a1, bb0.y), 0.f);
    float v2 = fmaxf(fmaf(dv, a2, bb0.z), 0.f);
    float v3 = fmaxf(fmaf(dv, a3, bb0.w), 0.f);
    float v4 = fmaxf(fmaf(dv, a4, bb1.x), 0.f);
    float v5 = fmaxf(fmaf(dv, a5, bb1.y), 0.f);
    float v6 = fmaxf(fmaf(dv, a6, bb1.z), 0.f);
    float v7 = fmaxf(fmaf(dv, a7, bb1.w), 0.f);

    if (layer != 0) {
        uint4 hv = d_hh[nd * 8 + p];
        float2 f;
        f = __half22float2(*(__half2*)&hv.x); v0 += f.x; v1 += f.y;
        f = __half22float2(*(__half2*)&hv.y); v2 += f.x; v3 += f.y;
        f = __half22float2(*(__half2*)&hv.z); v4 += f.x; v5 += f.y;
        f = __half22float2(*(__half2*)&hv.w); v6 += f.x; v7 += f.y;
    }

    uint4 o;
    __half2 t0, t1;
    t0 = __float22half2_rn(make_float2(v0, v1));
    t1 = __float22half2_rn(make_float2(v2, v3));
    o.x = *(unsigned*)&t0; o.y = *(unsigned*)&t1;
    t0 = __float22half2_rn(make_float2(v4, v5));
    t1 = __float22half2_rn(make_float2(v6, v7));
    o.z = *(unsigned*)&t0; o.w = *(unsigned*)&t1;
    d_hh[nd * 8 + p] = o;
}

// ---------------------------------------------------------------- fused pool + MLP
// One warp per graph. batch is sorted -> binary search the node range, reduce
// 64 channels (2/lane), then run the 64->32->16->1 MLP within the warp.
__global__ void __launch_bounds__(256) k_poolmlp(const int* __restrict__ batch,
                                                 const float* __restrict__ w1, const float* __restrict__ b1,
                                                 const float* __restrict__ w2, const float* __restrict__ b2,
                                                 const float* __restrict__ w3, const float* __restrict__ b3,
                                                 float* __restrict__ out, int n) {
    __shared__ float sg[8][64];
    __shared__ float sa[8][32];

    int wlocal = threadIdx.x >> 5;
    int g = (blockIdx.x * blockDim.x + threadIdx.x) >> 5;
    int lane = threadIdx.x & 31;
    if (g >= GG) return;

    // lower_bound(batch, g) and lower_bound(batch, g+1)
    int lo = 0, hi = n;
    while (lo < hi) { int m = (lo + hi) >> 1; if (__ldg(&batch[m]) < g) lo = m + 1; else hi = m; }
    int lo2 = lo, hi2 = n;
    while (lo2 < hi2) { int m = (lo2 + hi2) >> 1; if (__ldg(&batch[m]) < g + 1) lo2 = m + 1; else hi2 = m; }
    int cnt = lo2 - lo;

    // mean over nodes: lane owns channels 2*lane, 2*lane+1 (one half2 = 4B per lane)
    const unsigned* h2 = (const unsigned*)d_hh;  // 32 half2 per node row
    float s0 = 0.f, s1 = 0.f;
    for (int i = lo; i < lo2; i++) {
        unsigned hv = __ldg(&h2[i * 32 + lane]);
        float2 f = __half22float2(*(__half2*)&hv);
        s0 += f.x; s1 += f.y;
    }
    float inv = 1.0f / fmaxf((float)cnt, 1.0f);
    sg[wlocal][lane * 2 + 0] = s0 * inv;
    sg[wlocal][lane * 2 + 1] = s1 * inv;
    __syncwarp();

    // layer1: 32 outputs, one per lane
    float acc1 = __ldg(&b1[lane]);
#pragma unroll 16
    for (int k = 0; k < 64; k++)
        acc1 = fmaf(sg[wlocal][k], __ldg(&w1[k * 32 + lane]), acc1);
    acc1 = fmaxf(acc1, 0.f);
    sa[wlocal][lane] = acc1;
    __syncwarp();

    // layer2: 16 outputs on lanes 0..15
    float acc2 = 0.f;
    if (lane < 16) {
        acc2 = __ldg(&b2[lane]);
#pragma unroll
        for (int k = 0; k < 32; k++)
            acc2 = fmaf(sa[wlocal][k], __ldg(&w2[k * 16 + lane]), acc2);
        acc2 = fmaxf(acc2, 0.f);
        acc2 *= __ldg(&w3[lane]);   // fold final dot
    }
    // warp reduce (lanes >=16 contribute 0)
#pragma unroll
    for (int o = 16; o > 0; o >>= 1) acc2 += __shfl_xor_sync(0xFFFFFFFFu, acc2, o);
    if (lane == 0) out[g] = acc2 + __ldg(&b3[0]);
}

// ---------------------------------------------------------------- launch
extern "C" void kernel_launch(void* const* d_in, const int* in_sizes, int n_in,
                              void* d_out, int out_size) {
    const int*   x      = (const int*)d_in[0];
    const int*   ei     = (const int*)d_in[1];
    const int*   batch  = (const int*)d_in[2];
    const float* emb    = (const float*)d_in[3];
    const float* conv_w = (const float*)d_in[4];
    const float* conv_b = (const float*)d_in[5];
    const float* w1     = (const float*)d_in[6];
    const float* b1     = (const float*)d_in[7];
    const float* w2     = (const float*)d_in[8];
    const float* b2     = (const float*)d_in[9];
    const float* w3     = (const float*)d_in[10];
    const float* b3     = (const float*)d_in[11];
    float* out = (float*)d_out;

    int n = in_sizes[0];       // 100000
    int e = in_sizes[1] / 2;   // 3200000
    const int* row = ei;       // source
    const int* col = ei + e;   // target

    int tb = 256;
    int g_n8 = (n * 8 + tb - 1) / tb;
    int g_e  = (e + tb - 1) / tb;
    int g_n  = (n + tb - 1) / tb;
    int g_rows = (n + 63) / 64;
    int nb_scan = (n + SCAN_BS - 1) / SCAN_BS;

    k_init<<<g_n, tb>>>(n);
    k_deg<<<g_e, tb>>>(col, e);
    k_scan1<<<nb_scan, SCAN_BS>>>(n);
    k_scan2<<<1, 1024>>>(nb_scan);
    k_scan3<<<g_n, tb>>>(n);
    k_fill<<<g_e, tb>>>(row, col, e);

    for (int l = 0; l < 3; l++) {
        k_gemm<<<g_rows, tb>>>(conv_w + l * HH * HH, x, emb, l, n);
        k_gather<<<g_n8, tb>>>(conv_b + l * HH, l, n);
    }

    k_poolmlp<<<(GG * 32 + tb - 1) / tb, tb>>>(batch, w1, b1, w2, b2, w3, b3, out, n);
}

// round 5
// speedup vs baseline: 1.7898x; 1.7898x over previous
#include <cuda_runtime.h>
#include <cuda_fp16.h>

#define NN 100000
#define EE 3200000
#define GG 2048
#define HH 64
#define SCAN_BS 512

// Scratch (device globals — no allocation allowed).
__device__ uint4   d_uh[(NN + 1) * 8];   // (h @ W) * dinv, fp16; row NN = dummy zeros (never written)
__device__ uint4   d_hh[NN * 8];         // node features h, fp16
__device__ float   d_dinv[NN];           // rsqrt(deg+1)
__device__ int     d_degi[NN];           // in-degree (re-zeroed at end of每 call by k_poolmlp)
__device__ int     d_off[NN];            // padded CSR offsets
__device__ int     d_epos[EE];           // per-edge rank within its target
__device__ int     d_csr[EE + 7 * NN];   // grouped sources, padded to x8 per node
__device__ volatile unsigned long long d_bstate[256];  // lookback scan state

// ---------------------------------------------------------------- deg (+ zero scan state)
__global__ void k_deg(const int* __restrict__ col, int e_cnt) {
    int e = blockIdx.x * blockDim.x + threadIdx.x;
    if (e < 256) d_bstate[e] = 0ULL;
    if (e >= e_cnt) return;
    d_epos[e] = atomicAdd(&d_degi[col[e]], 1);
}

// ---------------------------------------------------------------- single-pass scan
__device__ __forceinline__ int warp_iscan(int v) {
    int lane = threadIdx.x & 31;
#pragma unroll
    for (int o = 1; o < 32; o <<= 1) {
        int t = __shfl_up_sync(0xFFFFFFFFu, v, o);
        if (lane >= o) v += t;
    }
    return v;
}

__global__ void __launch_bounds__(SCAN_BS) k_scan(int n) {
    __shared__ int ws[16];
    __shared__ int s_prefix;
    int t = threadIdx.x, bid = blockIdx.x;
    int lane = t & 31, wid = t >> 5;
    int i = bid * SCAN_BS + t;

    int deg = (i < n) ? d_degi[i] : 0;
    int pdeg = (deg + 7) & ~7;

    int s = warp_iscan(pdeg);
    if (lane == 31) ws[wid] = s;
    __syncthreads();
    if (wid == 0) {
        int wv = (lane < 16) ? ws[lane] : 0;
        int wsum = warp_iscan(wv);
        if (lane < 16) ws[lane] = wsum;
    }
    __syncthreads();
    int base = (wid > 0) ? ws[wid - 1] : 0;
    int incl = base + s;                 // inclusive scan of pdeg within block
    int total = ws[15];                  // block aggregate

    // warp 0: publish + lookback
    if (wid == 0) {
        if (bid == 0) {
            if (lane == 0) {
                s_prefix = 0;
                d_bstate[0] = (2ULL << 32) | (unsigned)total;
            }
        } else {
            if (lane == 0)
                d_bstate[bid] = (1ULL << 32) | (unsigned)total;
            long long run = 0;
            int wbase = bid;
            while (true) {
                int b = wbase - 32 + lane;
                unsigned long long st;
                if (b >= 0) {
                    do { st = d_bstate[b]; } while ((st >> 32) == 0);
                } else {
                    st = (2ULL << 32);   // boundary: prefix 0
                }
                unsigned pm = __ballot_sync(0xFFFFFFFFu, (st >> 32) == 2u);
                if (pm) {
                    int lead = 31 - __clz(pm);   // nearest predecessor with full prefix
                    long long v = (lane >= lead) ? (long long)(unsigned)st : 0;
#pragma unroll
                    for (int o = 16; o > 0; o >>= 1) v += __shfl_xor_sync(0xFFFFFFFFu, v, o);
                    run += v;
                    break;
                } else {
                    long long v = (long long)(unsigned)st;
#pragma unroll
                    for (int o = 16; o > 0; o >>= 1) v += __shfl_xor_sync(0xFFFFFFFFu, v, o);
                    run += v;
                    wbase -= 32;
                }
            }
            if (lane == 0) {
                s_prefix = (int)run;
                d_bstate[bid] = (2ULL << 32) | (unsigned)(run + total);
            }
        }
    }
    __syncthreads();

    if (i < n) {
        d_off[i] = s_prefix + incl - pdeg;   // exclusive padded offset
        d_dinv[i] = rsqrtf((float)deg + 1.0f);
    }
}

// CSR fill: plain store via precomputed rank (no atomics)
__global__ void k_fill(const int* __restrict__ rowi, const int* __restrict__ coli, int e_cnt) {
    int e = blockIdx.x * blockDim.x + threadIdx.x;
    if (e >= e_cnt) return;
    d_csr[__ldg(&d_off[coli[e]]) + d_epos[e]] = rowi[e];
}

// pad slots [off+deg, off+pdeg) -> dummy node NN (zero row)
__global__ void k_pad(int n) {
    int i = blockIdx.x * blockDim.x + threadIdx.x;
    if (i >= n) return;
    int off = d_off[i];
    int deg = d_degi[i];
    int pd = (deg + 7) & ~7;
    for (int k = deg; k < pd; k++) d_csr[off + k] = NN;
}

// ---------------------------------------------------------------- GEMM: u = (h @ W) * dinv -> fp16
// Block tile: 128 rows x 64 cols. Warp w: rows 32*(w&3)+lane, cols 32*(w>>2)..+32.
// Weights broadcast from smem (all lanes same address); h fp16 in smem, stride 66 (conflict-free).
__global__ void __launch_bounds__(256) k_gemm(const float* __restrict__ W,
                                              const int* __restrict__ x,
                                              const float* __restrict__ emb,
                                              int layer, int n) {
    __shared__ float4 sW[64 * 16];        // 16 KB
    __shared__ __half sh[128 * 66];       // 16.9 KB

    int tid = threadIdx.x;
    int row0 = blockIdx.x * 128;

    const float4* W4 = (const float4*)W;
#pragma unroll
    for (int i = 0; i < 4; i++) sW[tid + 256 * i] = W4[tid + 256 * i];

    if (layer == 0) {
        const float4* emb4 = (const float4*)emb;
#pragma unroll
        for (int i = 0; i < 8; i++) {
            int idx = tid + 256 * i;
            int r = idx >> 4, c4 = idx & 15;
            int grow = row0 + r;
            float4 v = make_float4(0.f, 0.f, 0.f, 0.f);
            if (grow < n) {
                int vx = __ldg(&x[grow]);
                v = __ldg(&emb4[vx * 16 + c4]);
            }
            __half2* dst = (__half2*)&sh[r * 66 + c4 * 4];
            dst[0] = __float22half2_rn(make_float2(v.x, v.y));
            dst[1] = __float22half2_rn(make_float2(v.z, v.w));
        }
    } else {
#pragma unroll
        for (int i = 0; i < 4; i++) {
            int idx = tid + 256 * i;
            int r = idx >> 3, c8 = idx & 7;
            int grow = row0 + r;
            uint4 uv = make_uint4(0, 0, 0, 0);
            if (grow < n) uv = d_hh[grow * 8 + c8];
            __half2* dst = (__half2*)&sh[r * 66 + c8 * 8];
            dst[0] = *(__half2*)&uv.x;
            dst[1] = *(__half2*)&uv.y;
            dst[2] = *(__half2*)&uv.z;
            dst[3] = *(__half2*)&uv.w;
        }
    }
    __syncthreads();

    int w = tid >> 5, lane = tid & 31;
    int r = (w & 3) * 32 + lane;     // row within tile
    int cq = (w >> 2) * 8;           // base float4-column (8 float4 = 32 cols)

    float4 acc[8];
#pragma unroll
    for (int j = 0; j < 8; j++) acc[j] = make_float4(0.f, 0.f, 0.f, 0.f);

    const __half* hrow = &sh[r * 66];
#pragma unroll 8
    for (int k = 0; k < 64; k++) {
        float hv = __half2float(hrow[k]);
#pragma unroll
        for (int j = 0; j < 8; j++) {
            float4 wv = sW[k * 16 + cq + j];
            acc[j].x = fmaf(hv, wv.x, acc[j].x);
            acc[j].y = fmaf(hv, wv.y, acc[j].y);
            acc[j].z = fmaf(hv, wv.z, acc[j].z);
            acc[j].w = fmaf(hv, wv.w, acc[j].w);
        }
    }

    int row = row0 + r;
    if (row < n) {
        float dv = __ldg(&d_dinv[row]);
#pragma unroll
        for (int m = 0; m < 4; m++) {
            float4 a = acc[2 * m], bq = acc[2 * m + 1];
            uint4 o;
            __half2 t0, t1;
            t0 = __float22half2_rn(make_float2(a.x * dv, a.y * dv));
            t1 = __float22half2_rn(make_float2(a.z * dv, a.w * dv));
            o.x = *(unsigned*)&t0; o.y = *(unsigned*)&t1;
            t0 = __float22half2_rn(make_float2(bq.x * dv, bq.y * dv));
            t1 = __float22half2_rn(make_float2(bq.z * dv, bq.w * dv));
            o.z = *(unsigned*)&t0; o.w = *(unsigned*)&t1;
            d_uh[row * 8 + (cq >> 1) + m] = o;
        }
    }
}

// ---------------------------------------------------------------- gather + epilogue (branch-free)
__global__ void __launch_bounds__(256) k_gather(const float* __restrict__ b, int layer, int n) {
    int idx = blockIdx.x * blockDim.x + threadIdx.x;
    int nd = idx >> 3;
    if (nd >= n) return;
    int p = idx & 7;
    int lane = threadIdx.x & 31;
    unsigned grpmask = 0xFFu << (lane & ~7);

    int beg = __ldg(&d_off[nd]);
    int deg = __ldg(&d_degi[nd]);

    float a0 = 0.f, a1 = 0.f, a2 = 0.f, a3 = 0.f,
          a4 = 0.f, a5 = 0.f, a6 = 0.f, a7 = 0.f;

#define ACC8(v) do {                                                  \
        float2 f;                                                     \
        f = __half22float2(*(__half2*)&(v).x); a0 += f.x; a1 += f.y;  \
        f = __half22float2(*(__half2*)&(v).y); a2 += f.x; a3 += f.y;  \
        f = __half22float2(*(__half2*)&(v).z); a4 += f.x; a5 += f.y;  \
        f = __half22float2(*(__half2*)&(v).w); a6 += f.x; a7 += f.y;  \
    } while (0)

    uint4 vs = d_uh[nd * 8 + p];  // self-loop term
    ACC8(vs);

    for (int k = 0; k < deg; k += 8) {
        int si = __ldg(&d_csr[beg + k + p]);   // pads point at zero row NN
#pragma unroll
        for (int j = 0; j < 8; j++) {
            int s = __shfl_sync(grpmask, si, j, 8);
            uint4 v = __ldg(&d_uh[s * 8 + p]);
            ACC8(v);
        }
    }
#undef ACC8

    float dv = __ldg(&d_dinv[nd]);
    const float4* b4 = (const float4*)b;
    float4 bb0 = __ldg(&b4[p * 2 + 0]);
    float4 bb1 = __ldg(&b4[p * 2 + 1]);

    float v0 = fmaxf(fmaf(dv, a0, bb0.x), 0.f);
    float v1 = fmaxf(fmaf(dv, a1, bb0.y), 0.f);
    float v2 = fmaxf(fmaf(dv, a2, bb0.z), 0.f);
    float v3 = fmaxf(fmaf(dv, a3, bb0.w), 0.f);
    float v4 = fmaxf(fmaf(dv, a4, bb1.x), 0.f);
    float v5 = fmaxf(fmaf(dv, a5, bb1.y), 0.f);
    float v6 = fmaxf(fmaf(dv, a6, bb1.z), 0.f);
    float v7 = fmaxf(fmaf(dv, a7, bb1.w), 0.f);

    if (layer != 0) {
        uint4 hv = d_hh[nd * 8 + p];
        float2 f;
        f = __half22float2(*(__half2*)&hv.x); v0 += f.x; v1 += f.y;
        f = __half22float2(*(__half2*)&hv.y); v2 += f.x; v3 += f.y;
        f = __half22float2(*(__half2*)&hv.z); v4 += f.x; v5 += f.y;
        f = __half22float2(*(__half2*)&hv.w); v6 += f.x; v7 += f.y;
    }

    uint4 o;
    __half2 t0, t1;
    t0 = __float22half2_rn(make_float2(v0, v1));
    t1 = __float22half2_rn(make_float2(v2, v3));
    o.x = *(unsigned*)&t0; o.y = *(unsigned*)&t1;
    t0 = __float22half2_rn(make_float2(v4, v5));
    t1 = __float22half2_rn(make_float2(v6, v7));
    o.z = *(unsigned*)&t0; o.w = *(unsigned*)&t1;
    d_hh[nd * 8 + p] = o;
}

// ---------------------------------------------------------------- fused pool + MLP (+ state cleanup)
__global__ void __launch_bounds__(256) k_poolmlp(const int* __restrict__ batch,
                                                 const float* __restrict__ w1, const float* __restrict__ b1,
                                                 const float* __restrict__ w2, const float* __restrict__ b2,
                                                 const float* __restrict__ w3, const float* __restrict__ b3,
                                                 float* __restrict__ out, int n) {
    __shared__ float sg[8][64];
    __shared__ float sa[8][32];

    // restore d_degi to zero for the next (identical) call — keeps every call's
    // starting state identical to the zero-initialized first call.
    int gt = blockIdx.x * blockDim.x + threadIdx.x;
    for (int i = gt; i < n; i += gridDim.x * blockDim.x) d_degi[i] = 0;

    int wlocal = threadIdx.x >> 5;
    int g = gt >> 5;
    int lane = threadIdx.x & 31;
    if (g >= GG) return;

    int lo = 0, hi = n;
    while (lo < hi) { int m = (lo + hi) >> 1; if (__ldg(&batch[m]) < g) lo = m + 1; else hi = m; }
    int lo2 = lo, hi2 = n;
    while (lo2 < hi2) { int m = (lo2 + hi2) >> 1; if (__ldg(&batch[m]) < g + 1) lo2 = m + 1; else hi2 = m; }
    int cnt = lo2 - lo;

    const unsigned* h2 = (const unsigned*)d_hh;
    float s0 = 0.f, s1 = 0.f;
    for (int i = lo; i < lo2; i++) {
        unsigned hv = __ldg(&h2[i * 32 + lane]);
        float2 f = __half22float2(*(__half2*)&hv);
        s0 += f.x; s1 += f.y;
    }
    float inv = 1.0f / fmaxf((float)cnt, 1.0f);
    sg[wlocal][lane * 2 + 0] = s0 * inv;
    sg[wlocal][lane * 2 + 1] = s1 * inv;
    __syncwarp();

    float acc1 = __ldg(&b1[lane]);
#pragma unroll 16
    for (int k = 0; k < 64; k++)
        acc1 = fmaf(sg[wlocal][k], __ldg(&w1[k * 32 + lane]), acc1);
    acc1 = fmaxf(acc1, 0.f);
    sa[wlocal][lane] = acc1;
    __syncwarp();

    float acc2 = 0.f;
    if (lane < 16) {
        acc2 = __ldg(&b2[lane]);
#pragma unroll
        for (int k = 0; k < 32; k++)
            acc2 = fmaf(sa[wlocal][k], __ldg(&w2[k * 16 + lane]), acc2);
        acc2 = fmaxf(acc2, 0.f);
        acc2 *= __ldg(&w3[lane]);
    }
#pragma unroll
    for (int o = 16; o > 0; o >>= 1) acc2 += __shfl_xor_sync(0xFFFFFFFFu, acc2, o);
    if (lane == 0) out[g] = acc2 + __ldg(&b3[0]);
}

// ---------------------------------------------------------------- launch
extern "C" void kernel_launch(void* const* d_in, const int* in_sizes, int n_in,
                              void* d_out, int out_size) {
    const int*   x      = (const int*)d_in[0];
    const int*   ei     = (const int*)d_in[1];
    const int*   batch  = (const int*)d_in[2];
    const float* emb    = (const float*)d_in[3];
    const float* conv_w = (const float*)d_in[4];
    const float* conv_b = (const float*)d_in[5];
    const float* w1     = (const float*)d_in[6];
    const float* b1     = (const float*)d_in[7];
    const float* w2     = (const float*)d_in[8];
    const float* b2     = (const float*)d_in[9];
    const float* w3     = (const float*)d_in[10];
    const float* b3     = (const float*)d_in[11];
    float* out = (float*)d_out;

    int n = in_sizes[0];       // 100000
    int e = in_sizes[1] / 2;   // 3200000
    const int* row = ei;       // source
    const int* col = ei + e;   // target

    int tb = 256;
    int g_n8 = (n * 8 + tb - 1) / tb;
    int g_e  = (e + tb - 1) / tb;
    int g_n  = (n + tb - 1) / tb;
    int g_rows = (n + 127) / 128;
    int nb_scan = (n + SCAN_BS - 1) / SCAN_BS;

    k_deg<<<g_e, tb>>>(col, e);                 // 0
    k_scan<<<nb_scan, SCAN_BS>>>(n);            // 1
    k_fill<<<g_e, tb>>>(row, col, e);           // 2
    k_gemm<<<g_rows, tb>>>(conv_w, x, emb, 0, n);   // 3 (ncu capture slot)
    k_pad<<<g_n, tb>>>(n);                      // 4
    k_gather<<<g_n8, tb>>>(conv_b, 0, n);       // 5
    for (int l = 1; l < 3; l++) {
        k_gemm<<<g_rows, tb>>>(conv_w + l * HH * HH, x, emb, l, n);
        k_gather<<<g_n8, tb>>>(conv_b + l * HH, l, n);
    }
    k_poolmlp<<<(GG * 32 + tb - 1) / tb, tb>>>(batch, w1, b1, w2, b2, w3, b3, out, n);
}

// round 6
// speedup vs baseline: 2.3617x; 1.3195x over previous
#include <cuda_runtime.h>
#include <cuda_fp16.h>

#define NN 100000
#define EE 3200000
#define GG 2048
#define HH 64
#define SCAN_BS 512

// Scratch (device globals — no allocation allowed).
__device__ uint4   d_uh[(NN + 1) * 8];   // (h @ W) * dinv, fp16; row NN = dummy zeros (never written)
__device__ uint4   d_hh[NN * 8];         // node features h, fp16
__device__ float   d_dinv[NN];           // rsqrt(deg+1)
__device__ int     d_degi[NN];           // in-degree (re-zeroed at end of call by k_poolmlp)
__device__ int     d_off[NN];            // padded CSR offsets
__device__ int     d_epos[EE];           // per-edge rank within its target
__device__ int     d_csr[EE + 7 * NN];   // grouped sources, padded to x8 per node
__device__ volatile unsigned long long d_bstate[256];  // lookback scan state

__device__ __forceinline__ unsigned smem_u32(const void* p) {
    return (unsigned)__cvta_generic_to_shared(p);
}

// ---------------------------------------------------------------- deg (+ zero scan state)
__global__ void k_deg(const int* __restrict__ col, int e_cnt) {
    int e = blockIdx.x * blockDim.x + threadIdx.x;
    if (e < 256) d_bstate[e] = 0ULL;
    if (e >= e_cnt) return;
    d_epos[e] = atomicAdd(&d_degi[col[e]], 1);
}

// ---------------------------------------------------------------- single-pass scan
__device__ __forceinline__ int warp_iscan(int v) {
    int lane = threadIdx.x & 31;
#pragma unroll
    for (int o = 1; o < 32; o <<= 1) {
        int t = __shfl_up_sync(0xFFFFFFFFu, v, o);
        if (lane >= o) v += t;
    }
    return v;
}

__global__ void __launch_bounds__(SCAN_BS) k_scan(int n) {
    __shared__ int ws[16];
    __shared__ int s_prefix;
    int t = threadIdx.x, bid = blockIdx.x;
    int lane = t & 31, wid = t >> 5;
    int i = bid * SCAN_BS + t;

    int deg = (i < n) ? d_degi[i] : 0;
    int pdeg = (deg + 7) & ~7;

    int s = warp_iscan(pdeg);
    if (lane == 31) ws[wid] = s;
    __syncthreads();
    if (wid == 0) {
        int wv = (lane < 16) ? ws[lane] : 0;
        int wsum = warp_iscan(wv);
        if (lane < 16) ws[lane] = wsum;
    }
    __syncthreads();
    int base = (wid > 0) ? ws[wid - 1] : 0;
    int incl = base + s;
    int total = ws[15];

    if (wid == 0) {
        if (bid == 0) {
            if (lane == 0) {
                s_prefix = 0;
                d_bstate[0] = (2ULL << 32) | (unsigned)total;
            }
        } else {
            if (lane == 0)
                d_bstate[bid] = (1ULL << 32) | (unsigned)total;
            long long run = 0;
            int wbase = bid;
            while (true) {
                int b = wbase - 32 + lane;
                unsigned long long st;
                if (b >= 0) {
                    do { st = d_bstate[b]; } while ((st >> 32) == 0);
                } else {
                    st = (2ULL << 32);
                }
                unsigned pm = __ballot_sync(0xFFFFFFFFu, (st >> 32) == 2u);
                if (pm) {
                    int lead = 31 - __clz(pm);
                    long long v = (lane >= lead) ? (long long)(unsigned)st : 0;
#pragma unroll
                    for (int o = 16; o > 0; o >>= 1) v += __shfl_xor_sync(0xFFFFFFFFu, v, o);
                    run += v;
                    break;
                } else {
                    long long v = (long long)(unsigned)st;
#pragma unroll
                    for (int o = 16; o > 0; o >>= 1) v += __shfl_xor_sync(0xFFFFFFFFu, v, o);
                    run += v;
                    wbase -= 32;
                }
            }
            if (lane == 0) {
                s_prefix = (int)run;
                d_bstate[bid] = (2ULL << 32) | (unsigned)(run + total);
            }
        }
    }
    __syncthreads();

    if (i < n) {
        d_off[i] = s_prefix + incl - pdeg;
        d_dinv[i] = rsqrtf((float)deg + 1.0f);
    }
}

// CSR fill: plain store via precomputed rank (no atomics)
__global__ void k_fill(const int* __restrict__ rowi, const int* __restrict__ coli, int e_cnt) {
    int e = blockIdx.x * blockDim.x + threadIdx.x;
    if (e >= e_cnt) return;
    d_csr[__ldg(&d_off[coli[e]]) + d_epos[e]] = rowi[e];
}

// pad slots [off+deg, off+pdeg) -> dummy node NN (zero row)
__global__ void k_pad(int n) {
    int i = blockIdx.x * blockDim.x + threadIdx.x;
    if (i >= n) return;
    int off = d_off[i];
    int deg = d_degi[i];
    int pd = (deg + 7) & ~7;
    for (int k = deg; k < pd; k++) d_csr[off + k] = NN;
}

// ---------------------------------------------------------------- GEMM (tensor core):
// u = (h @ W) * dinv -> fp16.  Block: 128 rows x 64 cols, 8 warps, warp = 16-row m-tile.
// mma.sync.m16n8k16 f16in/f32acc; A,B staged in smem at stride 72 halves (conflict-free ldmatrix).
__global__ void __launch_bounds__(256) k_gemm(const float* __restrict__ W,
                                              const int* __restrict__ x,
                                              const float* __restrict__ emb,
                                              int layer, int n) {
    __shared__ __half sA[128 * 72];   // h rows, fp16
    __shared__ __half sB[64 * 72];    // W [k][n], fp16

    int tid = threadIdx.x;
    int row0 = blockIdx.x * 128;

    // W fp32 -> fp16
    const float4* W4 = (const float4*)W;
#pragma unroll
    for (int i = 0; i < 4; i++) {
        int idx = tid + 256 * i;
        int k = idx >> 4, c4 = idx & 15;
        float4 v = W4[k * 16 + c4];
        __half2* dst = (__half2*)&sB[k * 72 + c4 * 4];
        dst[0] = __float22half2_rn(make_float2(v.x, v.y));
        dst[1] = __float22half2_rn(make_float2(v.z, v.w));
    }

    if (layer == 0) {
        const float4* emb4 = (const float4*)emb;
#pragma unroll
        for (int i = 0; i < 8; i++) {
            int idx = tid + 256 * i;
            int r = idx >> 4, c4 = idx & 15;
            int grow = row0 + r;
            float4 v = make_float4(0.f, 0.f, 0.f, 0.f);
            if (grow < n) {
                int vx = __ldg(&x[grow]);
                v = __ldg(&emb4[vx * 16 + c4]);
            }
            __half2* dst = (__half2*)&sA[r * 72 + c4 * 4];
            dst[0] = __float22half2_rn(make_float2(v.x, v.y));
            dst[1] = __float22half2_rn(make_float2(v.z, v.w));
        }
    } else {
#pragma unroll
        for (int i = 0; i < 4; i++) {
            int idx = tid + 256 * i;
            int r = idx >> 3, c8 = idx & 7;
            int grow = row0 + r;
            uint4 uv = make_uint4(0, 0, 0, 0);
            if (grow < n) uv = d_hh[grow * 8 + c8];
            *(uint4*)&sA[r * 72 + c8 * 8] = uv;   // 144B row stride -> 16B aligned
        }
    }
    __syncthreads();

    int w = tid >> 5, lane = tid & 31;
    int m0 = w * 16;

    float acc[8][4];
#pragma unroll
    for (int j = 0; j < 8; j++) {
        acc[j][0] = 0.f; acc[j][1] = 0.f; acc[j][2] = 0.f; acc[j][3] = 0.f;
    }

    int sub = lane >> 3, lrow = lane & 7;
    int bl = lane & 15;

#pragma unroll
    for (int kk = 0; kk < 4; kk++) {
        // A fragment: 16x16 tile at (m0, kk*16), ldmatrix x4
        unsigned aaddr = smem_u32(&sA[(m0 + (sub & 1) * 8 + lrow) * 72 + kk * 16 + (sub >> 1) * 8]);
        unsigned a0, a1, a2, a3;
        asm volatile("ldmatrix.sync.aligned.m8n8.x4.shared.b16 {%0,%1,%2,%3}, [%4];"
                     : "=r"(a0), "=r"(a1), "=r"(a2), "=r"(a3) : "r"(aaddr));
#pragma unroll
        for (int j = 0; j < 8; j++) {
            // B fragment: 16x8 tile at (kk*16, j*8), row-major [k][n] -> x2.trans
            unsigned baddr = smem_u32(&sB[(kk * 16 + (bl >> 3) * 8 + (bl & 7)) * 72 + j * 8]);
            unsigned b0, b1;
            asm volatile("ldmatrix.sync.aligned.m8n8.x2.trans.shared.b16 {%0,%1}, [%2];"
                         : "=r"(b0), "=r"(b1) : "r"(baddr));
            asm volatile("mma.sync.aligned.m16n8k16.row.col.f32.f16.f16.f32 "
                         "{%0,%1,%2,%3},{%4,%5,%6,%7},{%8,%9},{%0,%1,%2,%3};"
                         : "+f"(acc[j][0]), "+f"(acc[j][1]), "+f"(acc[j][2]), "+f"(acc[j][3])
                         : "r"(a0), "r"(a1), "r"(a2), "r"(a3), "r"(b0), "r"(b1));
        }
    }

    // epilogue: D lane map: c0/c1 -> row l>>2, cols (l&3)*2,+1 ; c2/c3 -> row+8
    int rA = row0 + m0 + (lane >> 2);
    int rB = rA + 8;
    float dvA = (rA < n) ? __ldg(&d_dinv[rA]) : 0.f;
    float dvB = (rB < n) ? __ldg(&d_dinv[rB]) : 0.f;
    __half2* U2 = (__half2*)d_uh;
    int ch = (lane & 3);  // half2 column index within 8-col tile = (l&3)
#pragma unroll
    for (int j = 0; j < 8; j++) {
        int c2 = j * 4 + ch;  // half2 index within 32 half2 per row
        if (rA < n) U2[rA * 32 + c2] = __float22half2_rn(make_float2(acc[j][0] * dvA, acc[j][1] * dvA));
        if (rB < n) U2[rB * 32 + c2] = __float22half2_rn(make_float2(acc[j][2] * dvB, acc[j][3] * dvB));
    }
}

// ---------------------------------------------------------------- gather + epilogue (branch-free)
__global__ void __launch_bounds__(256) k_gather(const float* __restrict__ b, int layer, int n) {
    int idx = blockIdx.x * blockDim.x + threadIdx.x;
    int nd = idx >> 3;
    if (nd >= n) return;
    int p = idx & 7;
    int lane = threadIdx.x & 31;
    unsigned grpmask = 0xFFu << (lane & ~7);

    int beg = __ldg(&d_off[nd]);
    int deg = __ldg(&d_degi[nd]);

    float a0 = 0.f, a1 = 0.f, a2 = 0.f, a3 = 0.f,
          a4 = 0.f, a5 = 0.f, a6 = 0.f, a7 = 0.f;

#define ACC8(v) do {                                                  \
        float2 f;                                                     \
        f = __half22float2(*(__half2*)&(v).x); a0 += f.x; a1 += f.y;  \
        f = __half22float2(*(__half2*)&(v).y); a2 += f.x; a3 += f.y;  \
        f = __half22float2(*(__half2*)&(v).z); a4 += f.x; a5 += f.y;  \
        f = __half22float2(*(__half2*)&(v).w); a6 += f.x; a7 += f.y;  \
    } while (0)

    uint4 vs = d_uh[nd * 8 + p];  // self-loop term
    ACC8(vs);

    for (int k = 0; k < deg; k += 8) {
        int si = __ldg(&d_csr[beg + k + p]);   // pads point at zero row NN
#pragma unroll
        for (int j = 0; j < 8; j++) {
            int s = __shfl_sync(grpmask, si, j, 8);
            uint4 v = __ldg(&d_uh[s * 8 + p]);
            ACC8(v);
        }
    }
#undef ACC8

    float dv = __ldg(&d_dinv[nd]);
    const float4* b4 = (const float4*)b;
    float4 bb0 = __ldg(&b4[p * 2 + 0]);
    float4 bb1 = __ldg(&b4[p * 2 + 1]);

    float v0 = fmaxf(fmaf(dv, a0, bb0.x), 0.f);
    float v1 = fmaxf(fmaf(dv, a1, bb0.y), 0.f);
    float v2 = fmaxf(fmaf(dv, a2, bb0.z), 0.f);
    float v3 = fmaxf(fmaf(dv, a3, bb0.w), 0.f);
    float v4 = fmaxf(fmaf(dv, a4, bb1.x), 0.f);
    float v5 = fmaxf(fmaf(dv, a5, bb1.y), 0.f);
    float v6 = fmaxf(fmaf(dv, a6, bb1.z), 0.f);
    float v7 = fmaxf(fmaf(dv, a7, bb1.w), 0.f);

    if (layer != 0) {
        uint4 hv = d_hh[nd * 8 + p];
        float2 f;
        f = __half22float2(*(__half2*)&hv.x); v0 += f.x; v1 += f.y;
        f = __half22float2(*(__half2*)&hv.y); v2 += f.x; v3 += f.y;
        f = __half22float2(*(__half2*)&hv.z); v4 += f.x; v5 += f.y;
        f = __half22float2(*(__half2*)&hv.w); v6 += f.x; v7 += f.y;
    }

    uint4 o;
    __half2 t0, t1;
    t0 = __float22half2_rn(make_float2(v0, v1));
    t1 = __float22half2_rn(make_float2(v2, v3));
    o.x = *(unsigned*)&t0; o.y = *(unsigned*)&t1;
    t0 = __float22half2_rn(make_float2(v4, v5));
    t1 = __float22half2_rn(make_float2(v6, v7));
    o.z = *(unsigned*)&t0; o.w = *(unsigned*)&t1;
    d_hh[nd * 8 + p] = o;
}

// ---------------------------------------------------------------- fused pool + MLP (+ state cleanup)
__global__ void __launch_bounds__(256) k_poolmlp(const int* __restrict__ batch,
                                                 const float* __restrict__ w1, const float* __restrict__ b1,
                                                 const float* __restrict__ w2, const float* __restrict__ b2,
                                                 const float* __restrict__ w3, const float* __restrict__ b3,
                                                 float* __restrict__ out, int n) {
    __shared__ float sg[8][64];
    __shared__ float sa[8][32];

    int gt = blockIdx.x * blockDim.x + threadIdx.x;
    for (int i = gt; i < n; i += gridDim.x * blockDim.x) d_degi[i] = 0;

    int wlocal = threadIdx.x >> 5;
    int g = gt >> 5;
    int lane = threadIdx.x & 31;
    if (g >= GG) return;

    int lo = 0, hi = n;
    while (lo < hi) { int m = (lo + hi) >> 1; if (__ldg(&batch[m]) < g) lo = m + 1; else hi = m; }
    int lo2 = lo, hi2 = n;
    while (lo2 < hi2) { int m = (lo2 + hi2) >> 1; if (__ldg(&batch[m]) < g + 1) lo2 = m + 1; else hi2 = m; }
    int cnt = lo2 - lo;

    const unsigned* h2 = (const unsigned*)d_hh;
    float s0 = 0.f, s1 = 0.f;
    for (int i = lo; i < lo2; i++) {
        unsigned hv = __ldg(&h2[i * 32 + lane]);
        float2 f = __half22float2(*(__half2*)&hv);
        s0 += f.x; s1 += f.y;
    }
    float inv = 1.0f / fmaxf((float)cnt, 1.0f);
    sg[wlocal][lane * 2 + 0] = s0 * inv;
    sg[wlocal][lane * 2 + 1] = s1 * inv;
    __syncwarp();

    float acc1 = __ldg(&b1[lane]);
#pragma unroll 16
    for (int k = 0; k < 64; k++)
        acc1 = fmaf(sg[wlocal][k], __ldg(&w1[k * 32 + lane]), acc1);
    acc1 = fmaxf(acc1, 0.f);
    sa[wlocal][lane] = acc1;
    __syncwarp();

    float acc2 = 0.f;
    if (lane < 16) {
        acc2 = __ldg(&b2[lane]);
#pragma unroll
        for (int k = 0; k < 32; k++)
            acc2 = fmaf(sa[wlocal][k], __ldg(&w2[k * 16 + lane]), acc2);
        acc2 = fmaxf(acc2, 0.f);
        acc2 *= __ldg(&w3[lane]);
    }
#pragma unroll
    for (int o = 16; o > 0; o >>= 1) acc2 += __shfl_xor_sync(0xFFFFFFFFu, acc2, o);
    if (lane == 0) out[g] = acc2 + __ldg(&b3[0]);
}

// ---------------------------------------------------------------- launch
extern "C" void kernel_launch(void* const* d_in, const int* in_sizes, int n_in,
                              void* d_out, int out_size) {
    const int*   x      = (const int*)d_in[0];
    const int*   ei     = (const int*)d_in[1];
    const int*   batch  = (const int*)d_in[2];
    const float* emb    = (const float*)d_in[3];
    const float* conv_w = (const float*)d_in[4];
    const float* conv_b = (const float*)d_in[5];
    const float* w1     = (const float*)d_in[6];
    const float* b1     = (const float*)d_in[7];
    const float* w2     = (const float*)d_in[8];
    const float* b2     = (const float*)d_in[9];
    const float* w3     = (const float*)d_in[10];
    const float* b3     = (const float*)d_in[11];
    float* out = (float*)d_out;

    int n = in_sizes[0];       // 100000
    int e = in_sizes[1] / 2;   // 3200000
    const int* row = ei;       // source
    const int* col = ei + e;   // target

    int tb = 256;
    int g_n8 = (n * 8 + tb - 1) / tb;
    int g_e  = (e + tb - 1) / tb;
    int g_n  = (n + tb - 1) / tb;
    int g_rows = (n + 127) / 128;
    int nb_scan = (n + SCAN_BS - 1) / SCAN_BS;

    k_deg<<<g_e, tb>>>(col, e);                 // 0
    k_scan<<<nb_scan, SCAN_BS>>>(n);            // 1
    k_fill<<<g_e, tb>>>(row, col, e);           // 2
    k_gemm<<<g_rows, tb>>>(conv_w, x, emb, 0, n);   // 3 (ncu capture slot)
    k_pad<<<g_n, tb>>>(n);                      // 4
    k_gather<<<g_n8, tb>>>(conv_b, 0, n);       // 5
    for (int l = 1; l < 3; l++) {
        k_gemm<<<g_rows, tb>>>(conv_w + l * HH * HH, x, emb, l, n);
        k_gather<<<g_n8, tb>>>(conv_b + l * HH, l, n);
    }
    k_poolmlp<<<(GG * 32 + tb - 1) / tb, tb>>>(batch, w1, b1, w2, b2, w3, b3, out, n);
}

// round 7
// speedup vs baseline: 2.5297x; 1.0712x over previous
#include <cuda_runtime.h>
#include <cuda_fp16.h>

#define NN 100000
#define EE 3200000
#define GG 2048
#define HH 64
#define SCAN_BS 512

// Scratch (device globals — no allocation allowed).
__device__ uint4   d_uh[(NN + 1) * 8];   // (h @ W) * dinv, fp16; row NN = dummy zeros (never written)
__device__ uint4   d_hh[NN * 8];         // node features h, fp16
__device__ float   d_dinv[NN];           // rsqrt(deg+1)
__device__ int     d_degi[NN];           // in-degree (re-zeroed at end of call by k_poolmlp)
__device__ int     d_off[NN];            // padded CSR offsets
__device__ unsigned short d_epos[EE];    // per-edge rank within its target
__device__ int     d_csr[EE + 7 * NN];   // grouped sources, padded to x8 per node
__device__ volatile unsigned long long d_bstate[256];  // lookback scan state

__device__ __forceinline__ unsigned smem_u32(const void* p) {
    return (unsigned)__cvta_generic_to_shared(p);
}

// ---------------------------------------------------------------- deg (+ zero scan state)
__global__ void k_deg(const int* __restrict__ col, int e_cnt) {
    int e = blockIdx.x * blockDim.x + threadIdx.x;
    if (e < 256) d_bstate[e] = 0ULL;
    if (e >= e_cnt) return;
    d_epos[e] = (unsigned short)atomicAdd(&d_degi[col[e]], 1);
}

// ---------------------------------------------------------------- single-pass scan (+ pad write)
__device__ __forceinline__ int warp_iscan(int v) {
    int lane = threadIdx.x & 31;
#pragma unroll
    for (int o = 1; o < 32; o <<= 1) {
        int t = __shfl_up_sync(0xFFFFFFFFu, v, o);
        if (lane >= o) v += t;
    }
    return v;
}

__global__ void __launch_bounds__(SCAN_BS) k_scan(int n) {
    __shared__ int ws[16];
    __shared__ int s_prefix;
    int t = threadIdx.x, bid = blockIdx.x;
    int lane = t & 31, wid = t >> 5;
    int i = bid * SCAN_BS + t;

    int deg = (i < n) ? d_degi[i] : 0;
    int pdeg = (deg + 7) & ~7;

    int s = warp_iscan(pdeg);
    if (lane == 31) ws[wid] = s;
    __syncthreads();
    if (wid == 0) {
        int wv = (lane < 16) ? ws[lane] : 0;
        int wsum = warp_iscan(wv);
        if (lane < 16) ws[lane] = wsum;
    }
    __syncthreads();
    int base = (wid > 0) ? ws[wid - 1] : 0;
    int incl = base + s;
    int total = ws[15];

    if (wid == 0) {
        if (bid == 0) {
            if (lane == 0) {
                s_prefix = 0;
                d_bstate[0] = (2ULL << 32) | (unsigned)total;
            }
        } else {
            if (lane == 0)
                d_bstate[bid] = (1ULL << 32) | (unsigned)total;
            long long run = 0;
            int wbase = bid;
            while (true) {
                int b = wbase - 32 + lane;
                unsigned long long st;
                if (b >= 0) {
                    do { st = d_bstate[b]; } while ((st >> 32) == 0);
                } else {
                    st = (2ULL << 32);
                }
                unsigned pm = __ballot_sync(0xFFFFFFFFu, (st >> 32) == 2u);
                if (pm) {
                    int lead = 31 - __clz(pm);
                    long long v = (lane >= lead) ? (long long)(unsigned)st : 0;
#pragma unroll
                    for (int o = 16; o > 0; o >>= 1) v += __shfl_xor_sync(0xFFFFFFFFu, v, o);
                    run += v;
                    break;
                } else {
                    long long v = (long long)(unsigned)st;
#pragma unroll
                    for (int o = 16; o > 0; o >>= 1) v += __shfl_xor_sync(0xFFFFFFFFu, v, o);
                    run += v;
                    wbase -= 32;
                }
            }
            if (lane == 0) {
                s_prefix = (int)run;
                d_bstate[bid] = (2ULL << 32) | (unsigned)(run + total);
            }
        }
    }
    __syncthreads();

    if (i < n) {
        int off = s_prefix + incl - pdeg;
        d_off[i] = off;
        d_dinv[i] = rsqrtf((float)deg + 1.0f);
        for (int k = deg; k < pdeg; k++) d_csr[off + k] = NN;  // pads -> zero row
    }
}

// CSR fill: plain store via precomputed rank (no atomics)
__global__ void k_fill(const int* __restrict__ rowi, const int* __restrict__ coli, int e_cnt) {
    int e = blockIdx.x * blockDim.x + threadIdx.x;
    if (e >= e_cnt) return;
    d_csr[__ldg(&d_off[coli[e]]) + (int)d_epos[e]] = rowi[e];
}

// ---------------------------------------------------------------- GEMM (tensor core):
// u = (h @ W) * dinv -> fp16.  Block: 128 rows x 64 cols, 8 warps, warp = 16-row m-tile.
// Epilogue staged through smem -> coalesced uint4 global stores.
__global__ void __launch_bounds__(256) k_gemm(const float* __restrict__ W,
                                              const int* __restrict__ x,
                                              const float* __restrict__ emb,
                                              int layer, int n) {
    __shared__ __half sA[128 * 72];   // h rows fp16; reused for D staging
    __shared__ __half sB[64 * 72];    // W [k][n] fp16

    int tid = threadIdx.x;
    int row0 = blockIdx.x * 128;

    // W fp32 -> fp16
    const float4* W4 = (const float4*)W;
#pragma unroll
    for (int i = 0; i < 4; i++) {
        int idx = tid + 256 * i;
        int k = idx >> 4, c4 = idx & 15;
        float4 v = W4[k * 16 + c4];
        __half2* dst = (__half2*)&sB[k * 72 + c4 * 4];
        dst[0] = __float22half2_rn(make_float2(v.x, v.y));
        dst[1] = __float22half2_rn(make_float2(v.z, v.w));
    }

    if (layer == 0) {
        const float4* emb4 = (const float4*)emb;
#pragma unroll
        for (int i = 0; i < 8; i++) {
            int idx = tid + 256 * i;
            int r = idx >> 4, c4 = idx & 15;
            int grow = row0 + r;
            float4 v = make_float4(0.f, 0.f, 0.f, 0.f);
            if (grow < n) {
                int vx = __ldg(&x[grow]);
                v = __ldg(&emb4[vx * 16 + c4]);
            }
            __half2* dst = (__half2*)&sA[r * 72 + c4 * 4];
            dst[0] = __float22half2_rn(make_float2(v.x, v.y));
            dst[1] = __float22half2_rn(make_float2(v.z, v.w));
        }
    } else {
#pragma unroll
        for (int i = 0; i < 4; i++) {
            int idx = tid + 256 * i;
            int r = idx >> 3, c8 = idx & 7;
            int grow = row0 + r;
            uint4 uv = make_uint4(0, 0, 0, 0);
            if (grow < n) uv = d_hh[grow * 8 + c8];
            *(uint4*)&sA[r * 72 + c8 * 8] = uv;
        }
    }
    __syncthreads();

    int w = tid >> 5, lane = tid & 31;
    int m0 = w * 16;
    int sub = lane >> 3, lrow = lane & 7;
    int bl = lane & 15;

    // hoist A fragments (4 k-tiles x 4 regs)
    unsigned af[4][4];
#pragma unroll
    for (int kk = 0; kk < 4; kk++) {
        unsigned aaddr = smem_u32(&sA[(m0 + (sub & 1) * 8 + lrow) * 72 + kk * 16 + (sub >> 1) * 8]);
        asm volatile("ldmatrix.sync.aligned.m8n8.x4.shared.b16 {%0,%1,%2,%3}, [%4];"
                     : "=r"(af[kk][0]), "=r"(af[kk][1]), "=r"(af[kk][2]), "=r"(af[kk][3])
                     : "r"(aaddr));
    }

    float acc[8][4];
#pragma unroll
    for (int j = 0; j < 8; j++) {
        acc[j][0] = 0.f; acc[j][1] = 0.f; acc[j][2] = 0.f; acc[j][3] = 0.f;
    }

#pragma unroll
    for (int kk = 0; kk < 4; kk++) {
#pragma unroll
        for (int j = 0; j < 8; j++) {
            unsigned baddr = smem_u32(&sB[(kk * 16 + (bl >> 3) * 8 + (bl & 7)) * 72 + j * 8]);
            unsigned b0, b1;
            asm volatile("ldmatrix.sync.aligned.m8n8.x2.trans.shared.b16 {%0,%1}, [%2];"
                         : "=r"(b0), "=r"(b1) : "r"(baddr));
            asm volatile("mma.sync.aligned.m16n8k16.row.col.f32.f16.f16.f32 "
                         "{%0,%1,%2,%3},{%4,%5,%6,%7},{%8,%9},{%0,%1,%2,%3};"
                         : "+f"(acc[j][0]), "+f"(acc[j][1]), "+f"(acc[j][2]), "+f"(acc[j][3])
                         : "r"(af[kk][0]), "r"(af[kk][1]), "r"(af[kk][2]), "r"(af[kk][3]),
                           "r"(b0), "r"(b1));
        }
    }
    __syncthreads();   // done reading sA -> reuse for D staging

    // stage D (scaled, fp16) into sA
    int rloc = m0 + (lane >> 2);
    int rA = row0 + rloc, rB = rA + 8;
    float dvA = (rA < n) ? __ldg(&d_dinv[rA]) : 0.f;
    float dvB = (rB < n) ? __ldg(&d_dinv[rB]) : 0.f;
    __half2* sA2 = (__half2*)sA;   // 36 half2 per row
    int ch = lane & 3;
#pragma unroll
    for (int j = 0; j < 8; j++) {
        int c2 = j * 4 + ch;
        sA2[rloc * 36 + c2]       = __float22half2_rn(make_float2(acc[j][0] * dvA, acc[j][1] * dvA));
        sA2[(rloc + 8) * 36 + c2] = __float22half2_rn(make_float2(acc[j][2] * dvB, acc[j][3] * dvB));
    }
    __syncthreads();

    // coalesced copy-out
#pragma unroll
    for (int i = 0; i < 4; i++) {
        int idx = tid + 256 * i;
        int r = idx >> 3, c8 = idx & 7;
        int grow = row0 + r;
        if (grow < n) d_uh[grow * 8 + c8] = *(uint4*)&sA[r * 72 + c8 * 8];
    }
}

// ---------------------------------------------------------------- gather + epilogue (branch-free)
__global__ void __launch_bounds__(256) k_gather(const float* __restrict__ b, int layer, int n) {
    int idx = blockIdx.x * blockDim.x + threadIdx.x;
    int nd = idx >> 3;
    if (nd >= n) return;
    int p = idx & 7;
    int lane = threadIdx.x & 31;
    unsigned grpmask = 0xFFu << (lane & ~7);

    int beg = __ldg(&d_off[nd]);
    int deg = __ldg(&d_degi[nd]);

    float a0 = 0.f, a1 = 0.f, a2 = 0.f, a3 = 0.f,
          a4 = 0.f, a5 = 0.f, a6 = 0.f, a7 = 0.f;

#define ACC8(v) do {                                                  \
        float2 f;                                                     \
        f = __half22float2(*(__half2*)&(v).x); a0 += f.x; a1 += f.y;  \
        f = __half22float2(*(__half2*)&(v).y); a2 += f.x; a3 += f.y;  \
        f = __half22float2(*(__half2*)&(v).z); a4 += f.x; a5 += f.y;  \
        f = __half22float2(*(__half2*)&(v).w); a6 += f.x; a7 += f.y;  \
    } while (0)

    uint4 vs = d_uh[nd * 8 + p];  // self-loop term
    ACC8(vs);

    for (int k = 0; k < deg; k += 8) {
        int si = __ldg(&d_csr[beg + k + p]);   // pads point at zero row NN
#pragma unroll
        for (int j = 0; j < 8; j++) {
            int s = __shfl_sync(grpmask, si, j, 8);
            uint4 v = __ldg(&d_uh[s * 8 + p]);
            ACC8(v);
        }
    }
#undef ACC8

    float dv = __ldg(&d_dinv[nd]);
    const float4* b4 = (const float4*)b;
    float4 bb0 = __ldg(&b4[p * 2 + 0]);
    float4 bb1 = __ldg(&b4[p * 2 + 1]);

    float v0 = fmaxf(fmaf(dv, a0, bb0.x), 0.f);
    float v1 = fmaxf(fmaf(dv, a1, bb0.y), 0.f);
    float v2 = fmaxf(fmaf(dv, a2, bb0.z), 0.f);
    float v3 = fmaxf(fmaf(dv, a3, bb0.w), 0.f);
    float v4 = fmaxf(fmaf(dv, a4, bb1.x), 0.f);
    float v5 = fmaxf(fmaf(dv, a5, bb1.y), 0.f);
    float v6 = fmaxf(fmaf(dv, a6, bb1.z), 0.f);
    float v7 = fmaxf(fmaf(dv, a7, bb1.w), 0.f);

    if (layer != 0) {
        uint4 hv = d_hh[nd * 8 + p];
        float2 f;
        f = __half22float2(*(__half2*)&hv.x); v0 += f.x; v1 += f.y;
        f = __half22float2(*(__half2*)&hv.y); v2 += f.x; v3 += f.y;
        f = __half22float2(*(__half2*)&hv.z); v4 += f.x; v5 += f.y;
        f = __half22float2(*(__half2*)&hv.w); v6 += f.x; v7 += f.y;
    }

    uint4 o;
    __half2 t0, t1;
    t0 = __float22half2_rn(make_float2(v0, v1));
    t1 = __float22half2_rn(make_float2(v2, v3));
    o.x = *(unsigned*)&t0; o.y = *(unsigned*)&t1;
    t0 = __float22half2_rn(make_float2(v4, v5));
    t1 = __float22half2_rn(make_float2(v6, v7));
    o.z = *(unsigned*)&t0; o.w = *(unsigned*)&t1;
    d_hh[nd * 8 + p] = o;
}

// ---------------------------------------------------------------- fused pool + MLP (+ state cleanup)
__global__ void __launch_bounds__(256) k_poolmlp(const int* __restrict__ batch,
                                                 const float* __restrict__ w1, const float* __restrict__ b1,
                                                 const float* __restrict__ w2, const float* __restrict__ b2,
                                                 const float* __restrict__ w3, const float* __restrict__ b3,
                                                 float* __restrict__ out, int n) {
    __shared__ float sg[8][64];
    __shared__ float sa[8][32];

    int gt = blockIdx.x * blockDim.x + threadIdx.x;
    for (int i = gt; i < n; i += gridDim.x * blockDim.x) d_degi[i] = 0;

    int wlocal = threadIdx.x >> 5;
    int g = gt >> 5;
    int lane = threadIdx.x & 31;
    if (g >= GG) return;

    int lo = 0, hi = n;
    while (lo < hi) { int m = (lo + hi) >> 1; if (__ldg(&batch[m]) < g) lo = m + 1; else hi = m; }
    int lo2 = lo, hi2 = n;
    while (lo2 < hi2) { int m = (lo2 + hi2) >> 1; if (__ldg(&batch[m]) < g + 1) lo2 = m + 1; else hi2 = m; }
    int cnt = lo2 - lo;

    const unsigned* h2 = (const unsigned*)d_hh;
    float s0 = 0.f, s1 = 0.f;
    for (int i = lo; i < lo2; i++) {
        unsigned hv = __ldg(&h2[i * 32 + lane]);
        float2 f = __half22float2(*(__half2*)&hv);
        s0 += f.x; s1 += f.y;
    }
    float inv = 1.0f / fmaxf((float)cnt, 1.0f);
    sg[wlocal][lane * 2 + 0] = s0 * inv;
    sg[wlocal][lane * 2 + 1] = s1 * inv;
    __syncwarp();

    float acc1 = __ldg(&b1[lane]);
#pragma unroll 16
    for (int k = 0; k < 64; k++)
        acc1 = fmaf(sg[wlocal][k], __ldg(&w1[k * 32 + lane]), acc1);
    acc1 = fmaxf(acc1, 0.f);
    sa[wlocal][lane] = acc1;
    __syncwarp();

    float acc2 = 0.f;
    if (lane < 16) {
        acc2 = __ldg(&b2[lane]);
#pragma unroll
        for (int k = 0; k < 32; k++)
            acc2 = fmaf(sa[wlocal][k], __ldg(&w2[k * 16 + lane]), acc2);
        acc2 = fmaxf(acc2, 0.f);
        acc2 *= __ldg(&w3[lane]);
    }
#pragma unroll
    for (int o = 16; o > 0; o >>= 1) acc2 += __shfl_xor_sync(0xFFFFFFFFu, acc2, o);
    if (lane == 0) out[g] = acc2 + __ldg(&b3[0]);
}

// ---------------------------------------------------------------- launch
extern "C" void kernel_launch(void* const* d_in, const int* in_sizes, int n_in,
                              void* d_out, int out_size) {
    const int*   x      = (const int*)d_in[0];
    const int*   ei     = (const int*)d_in[1];
    const int*   batch  = (const int*)d_in[2];
    const float* emb    = (const float*)d_in[3];
    const float* conv_w = (const float*)d_in[4];
    const float* conv_b = (const float*)d_in[5];
    const float* w1     = (const float*)d_in[6];
    const float* b1     = (const float*)d_in[7];
    const float* w2     = (const float*)d_in[8];
    const float* b2     = (const float*)d_in[9];
    const float* w3     = (const float*)d_in[10];
    const float* b3     = (const float*)d_in[11];
    float* out = (float*)d_out;

    int n = in_sizes[0];       // 100000
    int e = in_sizes[1] / 2;   // 3200000
    const int* row = ei;       // source
    const int* col = ei + e;   // target

    int tb = 256;
    int g_n8 = (n * 8 + tb - 1) / tb;
    int g_e  = (e + tb - 1) / tb;
    int g_rows = (n + 127) / 128;
    int nb_scan = (n + SCAN_BS - 1) / SCAN_BS;

    k_deg<<<g_e, tb>>>(col, e);                 // 0
    k_scan<<<nb_scan, SCAN_BS>>>(n);            // 1
    k_fill<<<g_e, tb>>>(row, col, e);           // 2
    k_gemm<<<g_rows, tb>>>(conv_w, x, emb, 0, n);   // 3 (ncu capture slot)
    k_gather<<<g_n8, tb>>>(conv_b, 0, n);       // 4
    for (int l = 1; l < 3; l++) {
        k_gemm<<<g_rows, tb>>>(conv_w + l * HH * HH, x, emb, l, n);
        k_gather<<<g_n8, tb>>>(conv_b + l * HH, l, n);
    }
    k_poolmlp<<<(GG * 32 + tb - 1) / tb, tb>>>(batch, w1, b1, w2, b2, w3, b3, out, n);
}